// round 10
// baseline (speedup 1.0000x reference)
#include <cuda_runtime.h>

// Problem constants
#define TT   64
#define BB   1024
#define DZc  256
#define DXc  64
#define DHc  1024

#define CROWS 16               // batch rows per 2-CTA cluster
#define NCTA  128
#define NTH   512

// padded smem row strides (floats): 16B-aligned, odd-row bank offset +4
#define ZS  260
#define HS  516
#define XBS 516
#define XSS 68

// Packed weight scratch (k-pair interleaved): W*[k][c] -> Wp[k/2][c][2]
__device__ float g_W1p[DZc * DHc];   // 1 MB
__device__ float g_Wxp[DXc * DHc];   // 256 KB
__device__ float g_W2p[DHc * DZc];   // 1 MB

// smem offsets (floats)
#define OFF_Z    0                    // 16*260 = 4160
#define OFF_ZIN  4160                 // 4160
#define OFF_KSUM 8320                 // 4096 (plain [16][256])
#define OFF_XB   12416                // 16*516 = 8256
#define OFF_H    20672                // 8256
#define OFF_PART 28928                // 2 ksegs * 4096 = 8192
#define OFF_PM   37120                // 2 bufs * 4096 = 8192 (exchange, dbl-buffered)
#define OFF_XS   45312                // 16*68 = 1088
#define OFF_WT   46400                // 512 (band)
#define OFF_B1   46912                // 512 (band)
#define OFF_B2   47424                // 256
#define OFF_BAR  47680                // mbarrier (8B)
#define SMEM_FLOATS 47688             // ~186.3 KB

typedef unsigned long long u64;

__device__ __forceinline__ void fma2(u64& acc, u64 a, u64 b)
{
    asm("fma.rn.f32x2 %0, %1, %2, %0;" : "+l"(acc) : "l"(a), "l"(b));
}
__device__ __forceinline__ float2 unpack2(u64 p)
{
    float2 v;
    asm("mov.b64 {%0, %1}, %2;" : "=f"(v.x), "=f"(v.y) : "l"(p));
    return v;
}
__device__ __forceinline__ float fast_tanh(float x)
{
    const float e = __expf(2.0f * x);
    return 1.0f - 2.0f * __fdividef(1.0f, 1.0f + e);
}
__device__ __forceinline__ unsigned smem_u32(const void* p)
{
    unsigned a;
    asm("{ .reg .u64 t; cvta.to.shared.u64 t, %1; cvt.u32.u64 %0, t; }"
        : "=r"(a) : "l"(p));
    return a;
}
__device__ __forceinline__ void mbar_init(unsigned addr, unsigned cnt)
{
    asm volatile("mbarrier.init.shared.b64 [%0], %1;" :: "r"(addr), "r"(cnt) : "memory");
}
__device__ __forceinline__ void mbar_arrive_peer(unsigned addr, unsigned peer)
{
    asm volatile(
        "{\n\t.reg .b32 ra;\n\t"
        "mapa.shared::cluster.u32 ra, %0, %1;\n\t"
        "mbarrier.arrive.shared::cluster.b64 _, [ra];\n\t}"
        :: "r"(addr), "r"(peer) : "memory");
}
__device__ __forceinline__ void mbar_wait(unsigned addr, unsigned parity)
{
    asm volatile(
        "{\n\t.reg .pred P;\n\t"
        "WL_%=:\n\t"
        "mbarrier.try_wait.parity.acquire.cluster.shared::cta.b64 P, [%0], %1, 0x989680;\n\t"
        "@P bra WD_%=;\n\t"
        "bra WL_%=;\n\t"
        "WD_%=:\n\t}"
        :: "r"(addr), "r"(parity) : "memory");
}
__device__ __forceinline__ float4 ld_dsmem4(unsigned addr)
{
    float4 v;
    asm volatile("ld.shared::cluster.v4.f32 {%0,%1,%2,%3}, [%4];"
                 : "=f"(v.x), "=f"(v.y), "=f"(v.z), "=f"(v.w) : "r"(addr));
    return v;
}
#define CLUSTER_SYNC() do { \
    asm volatile("barrier.cluster.arrive.aligned;" ::: "memory"); \
    asm volatile("barrier.cluster.wait.aligned;"   ::: "memory"); } while (0)

// ---------------------------------------------------------------------------
// Weight pack kernel (unchanged layouts)
// ---------------------------------------------------------------------------
__global__ void pack_kernel(const float* __restrict__ W1,
                            const float* __restrict__ Wx,
                            const float* __restrict__ W2)
{
    const int i = blockIdx.x * blockDim.x + threadIdx.x;   // [0, 262144)
    {
        const int kp = i >> 11, rem = i & 2047;
        const int c = rem >> 1, par = rem & 1;
        g_W1p[i] = W1[(2 * kp + par) * DHc + c];
    }
    {
        const int kp = i >> 9, rem = i & 511;
        const int j = rem >> 1, par = rem & 1;
        g_W2p[i] = W2[(2 * kp + par) * DZc + j];
    }
    if (i < DXc * DHc) {
        const int kp = i >> 11, rem = i & 2047;
        const int c = rem >> 1, par = rem & 1;
        g_Wxp[i] = Wx[(2 * kp + par) * DHc + c];
    }
}

// ---------------------------------------------------------------------------
// k-packed GEMM accumulate. Thread: 2 cols x 8 rows (rows 2m+rp), K=KTOT.
// Wcol pre-offset to this thread's column pair; WROW = floats per kp-row.
// Lanes i and i+16 share the SAME Wcol address (coalescer dedups wavefronts).
// ---------------------------------------------------------------------------
template <int KTOT, int INSTRIDE, int WROW>
__device__ __forceinline__ void gemm_acc(
    const float* in_s, int rp, const float* __restrict__ Wcol, u64* a0, u64* a1)
{
#pragma unroll
    for (int m = 0; m < 8; ++m) { a0[m] = 0ull; a1[m] = 0ull; }

#pragma unroll 4
    for (int k = 0; k < KTOT; k += 4) {
        const ulonglong2 wA = *(const ulonglong2*)(Wcol + (k >> 1) * WROW);
        const ulonglong2 wB = *(const ulonglong2*)(Wcol + ((k >> 1) + 1) * WROW);
#pragma unroll
        for (int m = 0; m < 8; ++m) {
            const ulonglong2 zp =
                *(const ulonglong2*)(in_s + (2 * m + rp) * INSTRIDE + k);
            fma2(a0[m], zp.x, wA.x);
            fma2(a1[m], zp.x, wA.y);
            fma2(a0[m], zp.y, wB.x);
            fma2(a1[m], zp.y, wB.y);
        }
    }
}

// ---------------------------------------------------------------------------
// Persistent cluster kernel: cluster pair (rank 0,1) owns 16 rows.
//   rank r: GEMM1 cols [512r,512r+512), GEMM2 k in [512r,512r+512).
//   h stays CTA-local; only GEMM2 partial [16][256] crosses via DSMEM.
//   Both CTAs redundantly compute the RK4 update (bitwise identical).
// ---------------------------------------------------------------------------
__global__ void __launch_bounds__(NTH, 1) __cluster_dims__(2, 1, 1)
ode_kernel(const float* __restrict__ z0, const float* __restrict__ t,
           const float* __restrict__ x,  const float* __restrict__ wt,
           const float* __restrict__ b1, const float* __restrict__ b2,
           float* __restrict__ out)
{
    extern __shared__ float sm[];
    float* z_s    = sm + OFF_Z;      // [16][260]
    float* zin_s  = sm + OFF_ZIN;    // [16][260]
    float* ksum_s = sm + OFF_KSUM;   // [16][256] plain
    float* xb_s   = sm + OFF_XB;     // [16][516] band cols
    float* h_s    = sm + OFF_H;      // [16][516] band cols
    float* part_s = sm + OFF_PART;   // [2][16][256]
    float* pm_s   = sm + OFF_PM;     // [2 bufs][4096]
    float* xs_s   = sm + OFF_XS;     // [16][68]
    float* wt_s   = sm + OFF_WT;     // band 512
    float* b1_s   = sm + OFF_B1;     // band 512
    float* b2_s   = sm + OFF_B2;     // 256

    const int tid  = threadIdx.x;
    const int lane = tid & 31;
    const int rp   = lane >> 4;                 // row parity (rows 2m+rp)
    const unsigned rank = blockIdx.x & 1;       // cluster ctarank (1-D, size 2)
    const int row0 = (blockIdx.x >> 1) * CROWS;

    const unsigned bar   = smem_u32(sm) + OFF_BAR * 4;
    unsigned pm_remote;                          // peer's pm_s base
    asm("mapa.shared::cluster.u32 %0, %1, %2;"
        : "=r"(pm_remote) : "r"(smem_u32(sm) + OFF_PM * 4), "r"(rank ^ 1u));

    if (tid == 0) mbar_init(bar, 1);
    __syncthreads();
    CLUSTER_SYNC();                              // peer bar init visible

    // cache band vectors
    if (tid < 512) {
        wt_s[tid] = wt[rank * 512 + tid];
        b1_s[tid] = b1[rank * 512 + tid];
    }
    if (tid < DZc) b2_s[tid] = b2[tid];
    // load z0 (full 16 rows, both CTAs)
#pragma unroll
    for (int i = 0; i < (CROWS * DZc) / NTH; ++i) {
        const int p = i * NTH + tid;
        z_s[(p >> 8) * ZS + (p & 255)] = z0[(row0 + (p >> 8)) * DZc + (p & 255)];
    }
    __syncthreads();

    // GEMM1 col-pair: warp w owns pairs [16w,16w+16), lanes i/i+16 share pair
    const int cp  = (tid >> 5) * 16 + (lane & 15);   // [0,256) band-local
    const int gc0 = (int)rank * 512 + cp * 2;        // global col
    // GEMM2: kseg + col pair
    const int kseg = tid >> 8;                       // 0..1
    const int jp   = ((tid >> 5) & 7) * 16 + (lane & 15);  // [0,128)
    const int j0   = jp * 2;
    const float* w2col =
        g_W2p + j0 * 2 + (((int)rank * 512 + kseg * 256) >> 1) * 512;

    int xph = 0, buf = 0;

    for (int step = 0; step < TT - 1; ++step) {
        const float t0 = __ldg(t + step);
        const float t1 = __ldg(t + step + 1);
        const float hstep = t1 - t0;
        const float tmid  = t0 + 0.5f * hstep;

        // stage x[step]: 16 rows x 64
#pragma unroll
        for (int i = 0; i < (CROWS * DXc) / NTH; ++i) {
            const int p = i * NTH + tid;
            xs_s[(p >> 6) * XSS + (p & 63)] = x[(step * BB + row0 + (p >> 6)) * DXc + (p & 63)];
        }
        __syncthreads();

        // xb = x @ Wx + b1 (band cols; thread reads/writes only its parity rows)
        {
            u64 a0[8], a1[8];
            gemm_acc<DXc, XSS, 2 * DHc>(xs_s, rp, g_Wxp + gc0 * 2, a0, a1);
            const float bb0 = b1_s[cp * 2], bb1 = b1_s[cp * 2 + 1];
#pragma unroll
            for (int m = 0; m < 8; ++m) {
                const float2 v0 = unpack2(a0[m]);
                const float2 v1 = unpack2(a1[m]);
                *(float2*)(xb_s + (2 * m + rp) * XBS + cp * 2) =
                    make_float2(v0.x + v0.y + bb0, v1.x + v1.y + bb1);
            }
        }
        // no barrier: each thread reads back exactly its own xb values

#pragma unroll 1
        for (int sub = 0; sub < 4; ++sub) {
            const float ts = (sub == 0) ? t0 : (sub == 3 ? t1 : tmid);
            const float* zi = (sub == 0) ? z_s : zin_s;

            // GEMM1 + tanh -> h band
            {
                u64 a0[8], a1[8];
                gemm_acc<DZc, ZS, 2 * DHc>(zi, rp, g_W1p + gc0 * 2, a0, a1);
                const float w0 = wt_s[cp * 2] * ts, w1 = wt_s[cp * 2 + 1] * ts;
#pragma unroll
                for (int m = 0; m < 8; ++m) {
                    const int r = 2 * m + rp;
                    const float2 v0  = unpack2(a0[m]);
                    const float2 v1  = unpack2(a1[m]);
                    const float2 xbv = *(const float2*)(xb_s + r * XBS + cp * 2);
                    *(float2*)(h_s + r * HS + cp * 2) =
                        make_float2(fast_tanh(v0.x + v0.y + xbv.x + w0),
                                    fast_tanh(v1.x + v1.y + xbv.y + w1));
                }
            }
            // kseg g reads h cols [256g,256g+256) == written by warps of same half
            asm volatile("bar.sync %0, 256;" :: "r"(kseg + 1) : "memory");

            // GEMM2 kseg (k local 256) -> partial
            {
                u64 a0[8], a1[8];
                gemm_acc<256, HS, 512>(h_s + kseg * 256, rp, w2col, a0, a1);
#pragma unroll
                for (int m = 0; m < 8; ++m) {
                    const int r = 2 * m + rp;
                    const float2 v0 = unpack2(a0[m]);
                    const float2 v1 = unpack2(a1[m]);
                    *(float2*)(part_s + kseg * 4096 + r * 256 + j0) =
                        make_float2(v0.x + v0.y, v1.x + v1.y);
                }
            }
            __syncthreads();

            // combine 2 ksegs -> pm[buf]
            {
                float* pm = pm_s + buf * 4096;
                const int pos = tid * 8;
#pragma unroll
                for (int i = 0; i < 2; ++i) {
                    const float4 u = *(const float4*)(part_s + pos + 4 * i);
                    const float4 v = *(const float4*)(part_s + 4096 + pos + 4 * i);
                    *(float4*)(pm + pos + 4 * i) =
                        make_float4(u.x + v.x, u.y + v.y, u.z + v.z, u.w + v.w);
                }
            }
            __syncthreads();
            if (tid == 0) mbar_arrive_peer(bar, rank ^ 1u);
            mbar_wait(bar, (unsigned)xph);

            // read peer partial + RK4 update (both CTAs identical arithmetic)
            {
                const float* pm = pm_s + buf * 4096;
                const unsigned rem = pm_remote + (unsigned)(buf * 4096 + tid * 8) * 4u;
                const int pos = tid * 8;
                const int r = pos >> 8, j = pos & 255;
                const int zi0 = r * ZS + j;
                const float4 pA0 = ld_dsmem4(rem);
                const float4 pA1 = ld_dsmem4(rem + 16);
#pragma unroll
                for (int i = 0; i < 2; ++i) {
                    const float4 lme = *(const float4*)(pm + pos + 4 * i);
                    const float4 pr  = (i == 0) ? pA0 : pA1;
                    const float4 bb  = *(const float4*)(b2_s + j + 4 * i);
                    const float v0 = lme.x + pr.x + bb.x;
                    const float v1 = lme.y + pr.y + bb.y;
                    const float v2 = lme.z + pr.z + bb.z;
                    const float v3 = lme.w + pr.w + bb.w;
                    const float4 zv = *(const float4*)(z_s + zi0 + 4 * i);
                    if (sub == 0) {
                        *(float4*)(ksum_s + pos + 4 * i) = make_float4(v0, v1, v2, v3);
                        const float c = 0.5f * hstep;
                        *(float4*)(zin_s + zi0 + 4 * i) =
                            make_float4(zv.x + c * v0, zv.y + c * v1,
                                        zv.z + c * v2, zv.w + c * v3);
                    } else if (sub == 1 || sub == 2) {
                        float4 ks = *(const float4*)(ksum_s + pos + 4 * i);
                        ks.x += 2.f * v0; ks.y += 2.f * v1;
                        ks.z += 2.f * v2; ks.w += 2.f * v3;
                        *(float4*)(ksum_s + pos + 4 * i) = ks;
                        const float c = (sub == 1) ? 0.5f * hstep : hstep;
                        *(float4*)(zin_s + zi0 + 4 * i) =
                            make_float4(zv.x + c * v0, zv.y + c * v1,
                                        zv.z + c * v2, zv.w + c * v3);
                    } else {
                        const float4 ks = *(const float4*)(ksum_s + pos + 4 * i);
                        const float c = hstep * (1.f / 6.f);
                        *(float4*)(z_s + zi0 + 4 * i) =
                            make_float4(zv.x + c * (ks.x + v0), zv.y + c * (ks.y + v1),
                                        zv.z + c * (ks.z + v2), zv.w + c * (ks.w + v3));
                    }
                }
            }
            xph ^= 1; buf ^= 1;
            __syncthreads();
        }
    }

    // each rank writes 8 of the 16 rows
#pragma unroll
    for (int i = 0; i < 2048 / NTH; ++i) {
        const int p = i * NTH + tid;
        const int r = (int)rank * 8 + (p >> 8), j = p & 255;
        out[(row0 + r) * DZc + j] = z_s[r * ZS + j];
    }
    CLUSTER_SYNC();   // peer may still DSMEM-read our smem
}

extern "C" void kernel_launch(void* const* d_in, const int* in_sizes, int n_in,
                              void* d_out, int out_size)
{
    const float* z0 = (const float*)d_in[0];
    const float* t  = (const float*)d_in[1];
    const float* x  = (const float*)d_in[2];
    const float* W1 = (const float*)d_in[3];
    const float* Wx = (const float*)d_in[4];
    const float* wt = (const float*)d_in[5];
    const float* b1 = (const float*)d_in[6];
    const float* W2 = (const float*)d_in[7];
    const float* b2 = (const float*)d_in[8];
    float* out = (float*)d_out;

    pack_kernel<<<(DZc * DHc) / 256, 256>>>(W1, Wx, W2);

    const size_t smem = SMEM_FLOATS * sizeof(float);   // ~186 KB
    cudaFuncSetAttribute(ode_kernel,
                         cudaFuncAttributeMaxDynamicSharedMemorySize, (int)smem);
    ode_kernel<<<NCTA, NTH, smem>>>(z0, t, x, wt, b1, b2, out);
}

// round 11
// speedup vs baseline: 1.1141x; 1.1141x over previous
#include <cuda_runtime.h>

// Problem constants
#define TT   64
#define BB   1024
#define DZc  256
#define DXc  64
#define DHc  1024

#define ROWS 8                 // batch rows per CTA
#define NCTA (BB / ROWS)       // 128 CTAs
#define NTH  256               // 8 warps; 255-reg budget -> 4-col tiles fit

// Packed weight scratch (k-pair interleaved): W*[k][c] -> Wp[k/2][c][2]
__device__ float g_W1p[DZc * DHc];   // 1 MB
__device__ float g_Wxp[DXc * DHc];   // 256 KB
__device__ float g_W2p[DHc * DZc];   // 1 MB

// Dynamic shared memory layout (floats)
#define OFF_Z    0                             // 2048
#define OFF_ZIN  (OFF_Z    + ROWS * DZc)       // 2048
#define OFF_KSUM (OFF_ZIN  + ROWS * DZc)       // 2048
#define OFF_XB   (OFF_KSUM + ROWS * DZc)       // 8192
#define OFF_H    (OFF_XB   + ROWS * DHc)       // 8192
#define OFF_PART (OFF_H    + ROWS * DHc)       // 4 * 2048 = 8192
#define OFF_XS   (OFF_PART + 4 * ROWS * DZc)   // 512
#define OFF_WT   (OFF_XS   + ROWS * DXc)       // 1024
#define OFF_B1   (OFF_WT   + DHc)              // 1024
#define OFF_B2   (OFF_B1   + DHc)              // 256
#define SMEM_FLOATS (OFF_B2 + DZc)             // 33536 floats = 131 KB

typedef unsigned long long u64;

__device__ __forceinline__ void fma2(u64& acc, u64 a, u64 b)
{
    asm("fma.rn.f32x2 %0, %1, %2, %0;" : "+l"(acc) : "l"(a), "l"(b));
}
__device__ __forceinline__ float2 unpack2(u64 p)
{
    float2 v;
    asm("mov.b64 {%0, %1}, %2;" : "=f"(v.x), "=f"(v.y) : "l"(p));
    return v;
}
__device__ __forceinline__ float fast_tanh(float x)
{
    const float e = __expf(2.0f * x);
    return 1.0f - 2.0f * __fdividef(1.0f, 1.0f + e);
}

// ---------------------------------------------------------------------------
// Weight pack kernel (layouts unchanged)
// ---------------------------------------------------------------------------
__global__ void pack_kernel(const float* __restrict__ W1,
                            const float* __restrict__ Wx,
                            const float* __restrict__ W2)
{
    const int i = blockIdx.x * blockDim.x + threadIdx.x;   // [0, 262144)
    {
        const int kp = i >> 11, rem = i & 2047;
        const int c = rem >> 1, par = rem & 1;
        g_W1p[i] = W1[(2 * kp + par) * DHc + c];
    }
    {
        const int kp = i >> 9, rem = i & 511;
        const int j = rem >> 1, par = rem & 1;
        g_W2p[i] = W2[(2 * kp + par) * DZc + j];
    }
    if (i < DXc * DHc) {
        const int kp = i >> 11, rem = i & 2047;
        const int c = rem >> 1, par = rem & 1;
        g_Wxp[i] = Wx[(2 * kp + par) * DHc + c];
    }
}

// ---------------------------------------------------------------------------
// k-packed 4-col GEMM accumulate: thread owns cols c0..c0+3, 8 rows, K=KTOT.
// Each z LDS.128 (4 k-values) now feeds 4 columns (was 2): z bytes/MAC halved.
// Wcol pre-offset to this thread's 4-col block (8 contiguous floats per kp).
// acc lanes = (even-k, odd-k) partial sums per (row, col).
// ---------------------------------------------------------------------------
template <int KTOT, int INSTRIDE, int WROW>
__device__ __forceinline__ void gemm_acc4(
    const float* in_s, const float* __restrict__ Wcol,
    u64* a0, u64* a1, u64* a2, u64* a3)
{
#pragma unroll
    for (int r = 0; r < ROWS; ++r) { a0[r] = 0ull; a1[r] = 0ull; a2[r] = 0ull; a3[r] = 0ull; }

#pragma unroll 4
    for (int k = 0; k < KTOT; k += 4) {
        const int kp = k >> 1;
        // kp+0: cols (c0,c1) and (c2,c3); kp+1: same
        const ulonglong2 wA = *(const ulonglong2*)(Wcol + kp * WROW);
        const ulonglong2 wB = *(const ulonglong2*)(Wcol + kp * WROW + 4);
        const ulonglong2 wC = *(const ulonglong2*)(Wcol + (kp + 1) * WROW);
        const ulonglong2 wD = *(const ulonglong2*)(Wcol + (kp + 1) * WROW + 4);
#pragma unroll
        for (int r = 0; r < ROWS; ++r) {
            const ulonglong2 zp = *(const ulonglong2*)(in_s + r * INSTRIDE + k);  // broadcast
            fma2(a0[r], zp.x, wA.x);
            fma2(a1[r], zp.x, wA.y);
            fma2(a2[r], zp.x, wB.x);
            fma2(a3[r], zp.x, wB.y);
            fma2(a0[r], zp.y, wC.x);
            fma2(a1[r], zp.y, wC.y);
            fma2(a2[r], zp.y, wD.x);
            fma2(a3[r], zp.y, wD.y);
        }
    }
}

// ---------------------------------------------------------------------------
// Persistent kernel, NTH=256.
//   GEMM1: thread owns cols [4t, 4t+4), full K (no split, no partials).
//   GEMM2: kseg = t>>6 (k band 256), cols [4(t&63), +4); kseg g reads exactly
//          the h band written by threads [64g, 64g+64) -> 64-thread barrier.
// ---------------------------------------------------------------------------
__global__ void __launch_bounds__(NTH, 1)
ode_kernel(const float* __restrict__ z0, const float* __restrict__ t,
           const float* __restrict__ x,  const float* __restrict__ wt,
           const float* __restrict__ b1, const float* __restrict__ b2,
           float* __restrict__ out)
{
    extern __shared__ float sm[];
    float* z_s    = sm + OFF_Z;
    float* zin_s  = sm + OFF_ZIN;
    float* ksum_s = sm + OFF_KSUM;
    float* xb_s   = sm + OFF_XB;
    float* h_s    = sm + OFF_H;
    float* part_s = sm + OFF_PART;
    float* xs_s   = sm + OFF_XS;
    float* wt_s   = sm + OFF_WT;
    float* b1_s   = sm + OFF_B1;
    float* b2_s   = sm + OFF_B2;

    const int tid  = threadIdx.x;
    const int c0   = tid * 4;              // GEMM1 4-col block
    const int kseg = tid >> 6;             // GEMM2 k segment 0..3
    const int j0   = (tid & 63) * 4;       // GEMM2 4-col block
    const int row0 = blockIdx.x * ROWS;

    const float* w1col = g_W1p + c0 * 2;
    const float* wxcol = g_Wxp + c0 * 2;
    const float* w2col = g_W2p + j0 * 2 + (kseg * 256 >> 1) * (2 * DZc);

    // cache small vectors; load z0 block
#pragma unroll
    for (int i = 0; i < 4; ++i) {
        wt_s[i * NTH + tid] = wt[i * NTH + tid];
        b1_s[i * NTH + tid] = b1[i * NTH + tid];
    }
    b2_s[tid] = b2[tid];
#pragma unroll
    for (int i = 0; i < (ROWS * DZc) / NTH; ++i)
        z_s[i * NTH + tid] = z0[row0 * DZc + i * NTH + tid];
    __syncthreads();

    for (int step = 0; step < TT - 1; ++step) {
        const float t0 = __ldg(t + step);
        const float t1 = __ldg(t + step + 1);
        const float hstep = t1 - t0;
        const float tmid  = t0 + 0.5f * hstep;

        // stage x[step] rows plain [r][DX]
        xs_s[tid]       = x[(step * BB + row0) * DXc + tid];
        xs_s[tid + NTH] = x[(step * BB + row0) * DXc + tid + NTH];
        __syncthreads();

        // ---- xb = x @ Wx + b1 (4-col, full K=64, epilogue direct) ----
        {
            u64 a0[ROWS], a1[ROWS], a2[ROWS], a3[ROWS];
            gemm_acc4<DXc, DXc, 2 * DHc>(xs_s, wxcol, a0, a1, a2, a3);
            const float4 bb = *(const float4*)(b1_s + c0);
#pragma unroll
            for (int r = 0; r < ROWS; ++r) {
                const float2 v0 = unpack2(a0[r]);
                const float2 v1 = unpack2(a1[r]);
                const float2 v2 = unpack2(a2[r]);
                const float2 v3 = unpack2(a3[r]);
                *(float4*)(xb_s + r * DHc + c0) =
                    make_float4(v0.x + v0.y + bb.x, v1.x + v1.y + bb.y,
                                v2.x + v2.y + bb.z, v3.x + v3.y + bb.w);
            }
        }
        // no barrier: each thread reads back only its own xb columns

#pragma unroll 1
        for (int sub = 0; sub < 4; ++sub) {
            const float ts = (sub == 0) ? t0 : (sub == 3 ? t1 : tmid);
            const float* zi = (sub == 0) ? z_s : zin_s;

            // GEMM1 (4-col, full K) + fused tanh -> h_s
            {
                u64 a0[ROWS], a1[ROWS], a2[ROWS], a3[ROWS];
                gemm_acc4<DZc, DZc, 2 * DHc>(zi, w1col, a0, a1, a2, a3);
                const float4 wtv = *(const float4*)(wt_s + c0);
                const float w0 = wtv.x * ts, w1 = wtv.y * ts;
                const float w2 = wtv.z * ts, w3 = wtv.w * ts;
#pragma unroll
                for (int r = 0; r < ROWS; ++r) {
                    const float2 v0  = unpack2(a0[r]);
                    const float2 v1  = unpack2(a1[r]);
                    const float2 v2  = unpack2(a2[r]);
                    const float2 v3  = unpack2(a3[r]);
                    const float4 xbv = *(const float4*)(xb_s + r * DHc + c0);
                    *(float4*)(h_s + r * DHc + c0) =
                        make_float4(fast_tanh(v0.x + v0.y + xbv.x + w0),
                                    fast_tanh(v1.x + v1.y + xbv.y + w1),
                                    fast_tanh(v2.x + v2.y + xbv.z + w2),
                                    fast_tanh(v3.x + v3.y + xbv.w + w3));
                }
            }
            // kseg g reads h cols [256g,256g+256) written by these same 64 threads
            asm volatile("bar.sync %0, 64;" :: "r"(kseg + 1) : "memory");

            // GEMM2 (4-col, k band 256) -> partial
            {
                u64 a0[ROWS], a1[ROWS], a2[ROWS], a3[ROWS];
                gemm_acc4<256, DHc, 2 * DZc>(h_s + kseg * 256, w2col, a0, a1, a2, a3);
#pragma unroll
                for (int r = 0; r < ROWS; ++r) {
                    const float2 v0 = unpack2(a0[r]);
                    const float2 v1 = unpack2(a1[r]);
                    const float2 v2 = unpack2(a2[r]);
                    const float2 v3 = unpack2(a3[r]);
                    *(float4*)(part_s + kseg * (ROWS * DZc) + r * DZc + j0) =
                        make_float4(v0.x + v0.y, v1.x + v1.y,
                                    v2.x + v2.y, v3.x + v3.y);
                }
            }
            __syncthreads();

            // combine 4 partials + RK4 update (thread owns 8 elements)
            {
                const int pos = tid * 8;              // r*DZc + j, 8 contiguous
                const int r = pos >> 8, j = pos & 255;
#pragma unroll
                for (int i = 0; i < 2; ++i) {
                    const int p = pos + 4 * i;
                    float4 s = *(const float4*)(part_s + p);
#pragma unroll
                    for (int seg = 1; seg < 4; ++seg) {
                        const float4 q = *(const float4*)(part_s + seg * (ROWS * DZc) + p);
                        s.x += q.x; s.y += q.y; s.z += q.z; s.w += q.w;
                    }
                    const float4 bb = *(const float4*)(b2_s + j + 4 * i);
                    const float v0 = s.x + bb.x, v1 = s.y + bb.y;
                    const float v2 = s.z + bb.z, v3 = s.w + bb.w;
                    const float4 zv = *(const float4*)(z_s + p);
                    if (sub == 0) {
                        *(float4*)(ksum_s + p) = make_float4(v0, v1, v2, v3);
                        const float c = 0.5f * hstep;
                        *(float4*)(zin_s + p) =
                            make_float4(zv.x + c * v0, zv.y + c * v1,
                                        zv.z + c * v2, zv.w + c * v3);
                    } else if (sub == 1 || sub == 2) {
                        float4 ks = *(const float4*)(ksum_s + p);
                        ks.x += 2.f * v0; ks.y += 2.f * v1;
                        ks.z += 2.f * v2; ks.w += 2.f * v3;
                        *(float4*)(ksum_s + p) = ks;
                        const float c = (sub == 1) ? 0.5f * hstep : hstep;
                        *(float4*)(zin_s + p) =
                            make_float4(zv.x + c * v0, zv.y + c * v1,
                                        zv.z + c * v2, zv.w + c * v3);
                    } else {
                        const float4 ks = *(const float4*)(ksum_s + p);
                        const float c = hstep * (1.f / 6.f);
                        *(float4*)(z_s + p) =
                            make_float4(zv.x + c * (ks.x + v0), zv.y + c * (ks.y + v1),
                                        zv.z + c * (ks.z + v2), zv.w + c * (ks.w + v3));
                    }
                }
                (void)r;
            }
            __syncthreads();
        }
    }

    // write z_final
#pragma unroll
    for (int i = 0; i < (ROWS * DZc) / NTH; ++i)
        out[row0 * DZc + i * NTH + tid] = z_s[i * NTH + tid];
}

extern "C" void kernel_launch(void* const* d_in, const int* in_sizes, int n_in,
                              void* d_out, int out_size)
{
    const float* z0 = (const float*)d_in[0];
    const float* t  = (const float*)d_in[1];
    const float* x  = (const float*)d_in[2];
    const float* W1 = (const float*)d_in[3];
    const float* Wx = (const float*)d_in[4];
    const float* wt = (const float*)d_in[5];
    const float* b1 = (const float*)d_in[6];
    const float* W2 = (const float*)d_in[7];
    const float* b2 = (const float*)d_in[8];
    float* out = (float*)d_out;

    pack_kernel<<<(DZc * DHc) / 256, 256>>>(W1, Wx, W2);

    const size_t smem = SMEM_FLOATS * sizeof(float);   // ~131 KB
    cudaFuncSetAttribute(ode_kernel,
                         cudaFuncAttributeMaxDynamicSharedMemorySize, (int)smem);
    ode_kernel<<<NCTA, NTH, smem>>>(z0, t, x, wt, b1, b2, out);
}

// round 12
// speedup vs baseline: 1.1958x; 1.0734x over previous
#include <cuda_runtime.h>

// Problem constants
#define TT   64
#define BB   1024
#define DZc  256
#define DXc  64
#define DHc  1024

#define ROWS 8                 // batch rows per CTA
#define NCTA (BB / ROWS)       // 128 CTAs
#define NTH  256               // 8 warps; 255-reg budget -> 4-col tiles fit

// Packed weight scratch, split-plane layout:
//   row kp (2 k-values) = [plane A: quads' cols 4q..4q+1][plane B: cols 4q+2..4q+3]
//   quad q in plane: 4 floats = (w[2kp][c],w[2kp+1][c],w[2kp][c+1],w[2kp+1][c+1])
// Lane q's 16B load is warp-contiguous -> 4 wavefronts per warp-LDG (dense).
__device__ float g_W1p[DZc * DHc];   // 1 MB   (128 kp-rows x 2048)
__device__ float g_Wxp[DXc * DHc];   // 256 KB (32 kp-rows x 2048)
__device__ float g_W2p[DHc * DZc];   // 1 MB   (512 kp-rows x 512)

// Dynamic shared memory layout (floats)
#define OFF_Z    0                             // 2048
#define OFF_ZIN  (OFF_Z    + ROWS * DZc)       // 2048
#define OFF_KSUM (OFF_ZIN  + ROWS * DZc)       // 2048
#define OFF_XB   (OFF_KSUM + ROWS * DZc)       // 8192
#define OFF_H    (OFF_XB   + ROWS * DHc)       // 8192
#define OFF_PART (OFF_H    + ROWS * DHc)       // 4 * 2048 = 8192
#define OFF_XS   (OFF_PART + 4 * ROWS * DZc)   // 512
#define OFF_WT   (OFF_XS   + ROWS * DXc)       // 1024
#define OFF_B1   (OFF_WT   + DHc)              // 1024
#define OFF_B2   (OFF_B1   + DHc)              // 256
#define SMEM_FLOATS (OFF_B2 + DZc)             // 33536 floats = 131 KB

typedef unsigned long long u64;

__device__ __forceinline__ void fma2(u64& acc, u64 a, u64 b)
{
    asm("fma.rn.f32x2 %0, %1, %2, %0;" : "+l"(acc) : "l"(a), "l"(b));
}
__device__ __forceinline__ float2 unpack2(u64 p)
{
    float2 v;
    asm("mov.b64 {%0, %1}, %2;" : "=f"(v.x), "=f"(v.y) : "l"(p));
    return v;
}
__device__ __forceinline__ float fast_tanh(float x)
{
    const float e = __expf(2.0f * x);
    return 1.0f - 2.0f * __fdividef(1.0f, 1.0f + e);
}

// ---------------------------------------------------------------------------
// Weight pack kernel: split-plane layout.
//   index i -> kp = i / WROW; rem = i % WROW; plane = rem / (WROW/2);
//   u = rem % (WROW/2); q = u>>2; s = u&3;
//   col = 4q + 2*plane + (s>>1); par = s&1;  val = W[(2kp+par)*NC + col]
// ---------------------------------------------------------------------------
__global__ void pack_kernel(const float* __restrict__ W1,
                            const float* __restrict__ Wx,
                            const float* __restrict__ W2)
{
    const int i = blockIdx.x * blockDim.x + threadIdx.x;   // [0, 262144)
    {   // W1p: WROW = 2048, NC = 1024
        const int kp = i >> 11, rem = i & 2047;
        const int plane = rem >> 10, u = rem & 1023;
        const int q = u >> 2, s = u & 3;
        const int col = q * 4 + plane * 2 + (s >> 1), par = s & 1;
        g_W1p[i] = W1[(2 * kp + par) * DHc + col];
    }
    {   // W2p: WROW = 512, NC = 256
        const int kp = i >> 9, rem = i & 511;
        const int plane = rem >> 8, u = rem & 255;
        const int q = u >> 2, s = u & 3;
        const int col = q * 4 + plane * 2 + (s >> 1), par = s & 1;
        g_W2p[i] = W2[(2 * kp + par) * DZc + col];
    }
    if (i < DXc * DHc) {   // Wxp: WROW = 2048, NC = 1024
        const int kp = i >> 11, rem = i & 2047;
        const int plane = rem >> 10, u = rem & 1023;
        const int q = u >> 2, s = u & 3;
        const int col = q * 4 + plane * 2 + (s >> 1), par = s & 1;
        g_Wxp[i] = Wx[(2 * kp + par) * DHc + col];
    }
}

// ---------------------------------------------------------------------------
// k-packed 4-col GEMM accumulate: thread owns cols c0..c0+3, 8 rows, K=KTOT.
// Wcol = plane-A base for this thread's quad (base + q*4); plane B at +PLANE.
// All four 16B weight loads are warp-dense (4 wavefronts each).
// ---------------------------------------------------------------------------
template <int KTOT, int INSTRIDE, int WROW, int PLANE>
__device__ __forceinline__ void gemm_acc4(
    const float* in_s, const float* __restrict__ Wcol,
    u64* a0, u64* a1, u64* a2, u64* a3)
{
#pragma unroll
    for (int r = 0; r < ROWS; ++r) { a0[r] = 0ull; a1[r] = 0ull; a2[r] = 0ull; a3[r] = 0ull; }

#pragma unroll 4
    for (int k = 0; k < KTOT; k += 4) {
        const int kp = k >> 1;
        const ulonglong2 wA = *(const ulonglong2*)(Wcol + kp * WROW);            // kp,   cols c0,c1
        const ulonglong2 wB = *(const ulonglong2*)(Wcol + kp * WROW + PLANE);    // kp,   cols c2,c3
        const ulonglong2 wC = *(const ulonglong2*)(Wcol + (kp + 1) * WROW);          // kp+1, c0,c1
        const ulonglong2 wD = *(const ulonglong2*)(Wcol + (kp + 1) * WROW + PLANE);  // kp+1, c2,c3
#pragma unroll
        for (int r = 0; r < ROWS; ++r) {
            const ulonglong2 zp = *(const ulonglong2*)(in_s + r * INSTRIDE + k);  // broadcast
            fma2(a0[r], zp.x, wA.x);
            fma2(a1[r], zp.x, wA.y);
            fma2(a2[r], zp.x, wB.x);
            fma2(a3[r], zp.x, wB.y);
            fma2(a0[r], zp.y, wC.x);
            fma2(a1[r], zp.y, wC.y);
            fma2(a2[r], zp.y, wD.x);
            fma2(a3[r], zp.y, wD.y);
        }
    }
}

// ---------------------------------------------------------------------------
// Persistent kernel, NTH=256 (structure identical to round 11).
// ---------------------------------------------------------------------------
__global__ void __launch_bounds__(NTH, 1)
ode_kernel(const float* __restrict__ z0, const float* __restrict__ t,
           const float* __restrict__ x,  const float* __restrict__ wt,
           const float* __restrict__ b1, const float* __restrict__ b2,
           float* __restrict__ out)
{
    extern __shared__ float sm[];
    float* z_s    = sm + OFF_Z;
    float* zin_s  = sm + OFF_ZIN;
    float* ksum_s = sm + OFF_KSUM;
    float* xb_s   = sm + OFF_XB;
    float* h_s    = sm + OFF_H;
    float* part_s = sm + OFF_PART;
    float* xs_s   = sm + OFF_XS;
    float* wt_s   = sm + OFF_WT;
    float* b1_s   = sm + OFF_B1;
    float* b2_s   = sm + OFF_B2;

    const int tid  = threadIdx.x;
    const int c0   = tid * 4;              // GEMM1 4-col block (quad q = tid)
    const int kseg = tid >> 6;             // GEMM2 k segment 0..3
    const int j0   = (tid & 63) * 4;       // GEMM2 4-col block (quad = tid&63)
    const int row0 = blockIdx.x * ROWS;

    const float* w1col = g_W1p + tid * 4;                          // plane-A quad base
    const float* wxcol = g_Wxp + tid * 4;
    const float* w2col = g_W2p + (tid & 63) * 4 + (kseg * 128) * 512;  // + kseg kp-rows

    // cache small vectors; load z0 block
#pragma unroll
    for (int i = 0; i < 4; ++i) {
        wt_s[i * NTH + tid] = wt[i * NTH + tid];
        b1_s[i * NTH + tid] = b1[i * NTH + tid];
    }
    b2_s[tid] = b2[tid];
#pragma unroll
    for (int i = 0; i < (ROWS * DZc) / NTH; ++i)
        z_s[i * NTH + tid] = z0[row0 * DZc + i * NTH + tid];
    __syncthreads();

    for (int step = 0; step < TT - 1; ++step) {
        const float t0 = __ldg(t + step);
        const float t1 = __ldg(t + step + 1);
        const float hstep = t1 - t0;
        const float tmid  = t0 + 0.5f * hstep;

        // stage x[step] rows plain [r][DX]
        xs_s[tid]       = x[(step * BB + row0) * DXc + tid];
        xs_s[tid + NTH] = x[(step * BB + row0) * DXc + tid + NTH];
        __syncthreads();

        // ---- xb = x @ Wx + b1 (4-col, full K=64, epilogue direct) ----
        {
            u64 a0[ROWS], a1[ROWS], a2[ROWS], a3[ROWS];
            gemm_acc4<DXc, DXc, 2 * DHc, DHc>(xs_s, wxcol, a0, a1, a2, a3);
            const float4 bb = *(const float4*)(b1_s + c0);
#pragma unroll
            for (int r = 0; r < ROWS; ++r) {
                const float2 v0 = unpack2(a0[r]);
                const float2 v1 = unpack2(a1[r]);
                const float2 v2 = unpack2(a2[r]);
                const float2 v3 = unpack2(a3[r]);
                *(float4*)(xb_s + r * DHc + c0) =
                    make_float4(v0.x + v0.y + bb.x, v1.x + v1.y + bb.y,
                                v2.x + v2.y + bb.z, v3.x + v3.y + bb.w);
            }
        }
        // no barrier: each thread reads back only its own xb columns

#pragma unroll 1
        for (int sub = 0; sub < 4; ++sub) {
            const float ts = (sub == 0) ? t0 : (sub == 3 ? t1 : tmid);
            const float* zi = (sub == 0) ? z_s : zin_s;

            // GEMM1 (4-col, full K) + fused tanh -> h_s
            {
                u64 a0[ROWS], a1[ROWS], a2[ROWS], a3[ROWS];
                gemm_acc4<DZc, DZc, 2 * DHc, DHc>(zi, w1col, a0, a1, a2, a3);
                const float4 wtv = *(const float4*)(wt_s + c0);
                const float w0 = wtv.x * ts, w1 = wtv.y * ts;
                const float w2 = wtv.z * ts, w3 = wtv.w * ts;
#pragma unroll
                for (int r = 0; r < ROWS; ++r) {
                    const float2 v0  = unpack2(a0[r]);
                    const float2 v1  = unpack2(a1[r]);
                    const float2 v2  = unpack2(a2[r]);
                    const float2 v3  = unpack2(a3[r]);
                    const float4 xbv = *(const float4*)(xb_s + r * DHc + c0);
                    *(float4*)(h_s + r * DHc + c0) =
                        make_float4(fast_tanh(v0.x + v0.y + xbv.x + w0),
                                    fast_tanh(v1.x + v1.y + xbv.y + w1),
                                    fast_tanh(v2.x + v2.y + xbv.z + w2),
                                    fast_tanh(v3.x + v3.y + xbv.w + w3));
                }
            }
            // kseg g reads h cols [256g,256g+256) written by these same 64 threads
            asm volatile("bar.sync %0, 64;" :: "r"(kseg + 1) : "memory");

            // GEMM2 (4-col, k band 256) -> partial
            {
                u64 a0[ROWS], a1[ROWS], a2[ROWS], a3[ROWS];
                gemm_acc4<256, DHc, 2 * DZc, DZc>(h_s + kseg * 256, w2col, a0, a1, a2, a3);
#pragma unroll
                for (int r = 0; r < ROWS; ++r) {
                    const float2 v0 = unpack2(a0[r]);
                    const float2 v1 = unpack2(a1[r]);
                    const float2 v2 = unpack2(a2[r]);
                    const float2 v3 = unpack2(a3[r]);
                    *(float4*)(part_s + kseg * (ROWS * DZc) + r * DZc + j0) =
                        make_float4(v0.x + v0.y, v1.x + v1.y,
                                    v2.x + v2.y, v3.x + v3.y);
                }
            }
            __syncthreads();

            // combine 4 partials + RK4 update (thread owns 8 elements)
            {
                const int pos = tid * 8;              // r*DZc + j, 8 contiguous
                const int j = pos & 255;
#pragma unroll
                for (int i = 0; i < 2; ++i) {
                    const int p = pos + 4 * i;
                    float4 s = *(const float4*)(part_s + p);
#pragma unroll
                    for (int seg = 1; seg < 4; ++seg) {
                        const float4 q = *(const float4*)(part_s + seg * (ROWS * DZc) + p);
                        s.x += q.x; s.y += q.y; s.z += q.z; s.w += q.w;
                    }
                    const float4 bb = *(const float4*)(b2_s + j + 4 * i);
                    const float v0 = s.x + bb.x, v1 = s.y + bb.y;
                    const float v2 = s.z + bb.z, v3 = s.w + bb.w;
                    const float4 zv = *(const float4*)(z_s + p);
                    if (sub == 0) {
                        *(float4*)(ksum_s + p) = make_float4(v0, v1, v2, v3);
                        const float c = 0.5f * hstep;
                        *(float4*)(zin_s + p) =
                            make_float4(zv.x + c * v0, zv.y + c * v1,
                                        zv.z + c * v2, zv.w + c * v3);
                    } else if (sub == 1 || sub == 2) {
                        float4 ks = *(const float4*)(ksum_s + p);
                        ks.x += 2.f * v0; ks.y += 2.f * v1;
                        ks.z += 2.f * v2; ks.w += 2.f * v3;
                        *(float4*)(ksum_s + p) = ks;
                        const float c = (sub == 1) ? 0.5f * hstep : hstep;
                        *(float4*)(zin_s + p) =
                            make_float4(zv.x + c * v0, zv.y + c * v1,
                                        zv.z + c * v2, zv.w + c * v3);
                    } else {
                        const float4 ks = *(const float4*)(ksum_s + p);
                        const float c = hstep * (1.f / 6.f);
                        *(float4*)(z_s + p) =
                            make_float4(zv.x + c * (ks.x + v0), zv.y + c * (ks.y + v1),
                                        zv.z + c * (ks.z + v2), zv.w + c * (ks.w + v3));
                    }
                }
            }
            __syncthreads();
        }
    }

    // write z_final
#pragma unroll
    for (int i = 0; i < (ROWS * DZc) / NTH; ++i)
        out[row0 * DZc + i * NTH + tid] = z_s[i * NTH + tid];
}

extern "C" void kernel_launch(void* const* d_in, const int* in_sizes, int n_in,
                              void* d_out, int out_size)
{
    const float* z0 = (const float*)d_in[0];
    const float* t  = (const float*)d_in[1];
    const float* x  = (const float*)d_in[2];
    const float* W1 = (const float*)d_in[3];
    const float* Wx = (const float*)d_in[4];
    const float* wt = (const float*)d_in[5];
    const float* b1 = (const float*)d_in[6];
    const float* W2 = (const float*)d_in[7];
    const float* b2 = (const float*)d_in[8];
    float* out = (float*)d_out;

    pack_kernel<<<(DZc * DHc) / 256, 256>>>(W1, Wx, W2);

    const size_t smem = SMEM_FLOATS * sizeof(float);   // ~131 KB
    cudaFuncSetAttribute(ode_kernel,
                         cudaFuncAttributeMaxDynamicSharedMemorySize, (int)smem);
    ode_kernel<<<NCTA, NTH, smem>>>(z0, t, x, wt, b1, b2, out);
}

// round 13
// speedup vs baseline: 1.3076x; 1.0934x over previous
#include <cuda_runtime.h>

// Problem constants
#define TT   64
#define BB   1024
#define DZc  256
#define DXc  64
#define DHc  1024

#define ROWS 7                 // batch rows per CTA (7*146=1022, last CTA: 2)
#define NCTA 147               // one wave on 148 SMs
#define NTH  256

// Packed weight scratch, split-plane layout (unchanged from round 12):
//   row kp = [plane A: quads' cols 4q..4q+1][plane B: cols 4q+2..4q+3]
__device__ float g_W1p[DZc * DHc];   // 1 MB
__device__ float g_Wxp[DXc * DHc];   // 256 KB
__device__ float g_W2p[DHc * DZc];   // 1 MB

// Dynamic shared memory layout (floats)
#define NZ   (ROWS * DZc)                      // 1792
#define NH   (ROWS * DHc)                      // 7168
#define OFF_Z    0
#define OFF_ZIN  (OFF_Z    + NZ)
#define OFF_KSUM (OFF_ZIN  + NZ)
#define OFF_XB   (OFF_KSUM + NZ)
#define OFF_H    (OFF_XB   + NH)
#define OFF_PART (OFF_H    + NH)               // 4 * NZ
#define OFF_XS   (OFF_PART + 4 * NZ)           // ROWS*DXc = 448
#define OFF_WT   (OFF_XS   + ROWS * DXc)
#define OFF_B1   (OFF_WT   + DHc)
#define OFF_B2   (OFF_B1   + DHc)
#define SMEM_FLOATS (OFF_B2 + DZc)             // 29632 floats = 116 KB

typedef unsigned long long u64;

__device__ __forceinline__ void fma2(u64& acc, u64 a, u64 b)
{
    asm("fma.rn.f32x2 %0, %1, %2, %0;" : "+l"(acc) : "l"(a), "l"(b));
}
__device__ __forceinline__ float2 unpack2(u64 p)
{
    float2 v;
    asm("mov.b64 {%0, %1}, %2;" : "=f"(v.x), "=f"(v.y) : "l"(p));
    return v;
}
__device__ __forceinline__ float fast_tanh(float x)
{
    const float e = __expf(2.0f * x);
    return 1.0f - 2.0f * __fdividef(1.0f, 1.0f + e);
}

// ---------------------------------------------------------------------------
// Weight pack kernel: split-plane layout (identical to round 12)
// ---------------------------------------------------------------------------
__global__ void pack_kernel(const float* __restrict__ W1,
                            const float* __restrict__ Wx,
                            const float* __restrict__ W2)
{
    const int i = blockIdx.x * blockDim.x + threadIdx.x;   // [0, 262144)
    {   // W1p: WROW = 2048, NC = 1024
        const int kp = i >> 11, rem = i & 2047;
        const int plane = rem >> 10, u = rem & 1023;
        const int q = u >> 2, s = u & 3;
        const int col = q * 4 + plane * 2 + (s >> 1), par = s & 1;
        g_W1p[i] = W1[(2 * kp + par) * DHc + col];
    }
    {   // W2p: WROW = 512, NC = 256
        const int kp = i >> 9, rem = i & 511;
        const int plane = rem >> 8, u = rem & 255;
        const int q = u >> 2, s = u & 3;
        const int col = q * 4 + plane * 2 + (s >> 1), par = s & 1;
        g_W2p[i] = W2[(2 * kp + par) * DZc + col];
    }
    if (i < DXc * DHc) {   // Wxp
        const int kp = i >> 11, rem = i & 2047;
        const int plane = rem >> 10, u = rem & 1023;
        const int q = u >> 2, s = u & 3;
        const int col = q * 4 + plane * 2 + (s >> 1), par = s & 1;
        g_Wxp[i] = Wx[(2 * kp + par) * DHc + col];
    }
}

// ---------------------------------------------------------------------------
// k-packed 4-col GEMM accumulate: thread owns cols c0..c0+3, 7 rows, K=KTOT.
// ---------------------------------------------------------------------------
template <int KTOT, int INSTRIDE, int WROW, int PLANE>
__device__ __forceinline__ void gemm_acc4(
    const float* in_s, const float* __restrict__ Wcol,
    u64* a0, u64* a1, u64* a2, u64* a3)
{
#pragma unroll
    for (int r = 0; r < ROWS; ++r) { a0[r] = 0ull; a1[r] = 0ull; a2[r] = 0ull; a3[r] = 0ull; }

#pragma unroll 4
    for (int k = 0; k < KTOT; k += 4) {
        const int kp = k >> 1;
        const ulonglong2 wA = *(const ulonglong2*)(Wcol + kp * WROW);
        const ulonglong2 wB = *(const ulonglong2*)(Wcol + kp * WROW + PLANE);
        const ulonglong2 wC = *(const ulonglong2*)(Wcol + (kp + 1) * WROW);
        const ulonglong2 wD = *(const ulonglong2*)(Wcol + (kp + 1) * WROW + PLANE);
#pragma unroll
        for (int r = 0; r < ROWS; ++r) {
            const ulonglong2 zp = *(const ulonglong2*)(in_s + r * INSTRIDE + k);  // broadcast
            fma2(a0[r], zp.x, wA.x);
            fma2(a1[r], zp.x, wA.y);
            fma2(a2[r], zp.x, wB.x);
            fma2(a3[r], zp.x, wB.y);
            fma2(a0[r], zp.y, wC.x);
            fma2(a1[r], zp.y, wC.y);
            fma2(a2[r], zp.y, wD.x);
            fma2(a3[r], zp.y, wD.y);
        }
    }
}

// ---------------------------------------------------------------------------
// Persistent kernel, 147 CTAs x 7 rows.  Last CTA: rows >= 1024 clamp their
// LOADS to row 1023 (finite data, results discarded) and skip their stores.
// ---------------------------------------------------------------------------
__global__ void __launch_bounds__(NTH, 1)
ode_kernel(const float* __restrict__ z0, const float* __restrict__ t,
           const float* __restrict__ x,  const float* __restrict__ wt,
           const float* __restrict__ b1, const float* __restrict__ b2,
           float* __restrict__ out)
{
    extern __shared__ float sm[];
    float* z_s    = sm + OFF_Z;      // [7][256]
    float* zin_s  = sm + OFF_ZIN;
    float* ksum_s = sm + OFF_KSUM;
    float* xb_s   = sm + OFF_XB;     // [7][1024]
    float* h_s    = sm + OFF_H;
    float* part_s = sm + OFF_PART;   // [4][7][256]
    float* xs_s   = sm + OFF_XS;     // [7][64]
    float* wt_s   = sm + OFF_WT;
    float* b1_s   = sm + OFF_B1;
    float* b2_s   = sm + OFF_B2;

    const int tid  = threadIdx.x;
    const int c0   = tid * 4;              // GEMM1 4-col block
    const int kseg = tid >> 6;             // GEMM2 k segment 0..3
    const int j0   = (tid & 63) * 4;       // GEMM2 4-col block
    const int row0 = blockIdx.x * ROWS;

    const float* w1col = g_W1p + tid * 4;
    const float* wxcol = g_Wxp + tid * 4;
    const float* w2col = g_W2p + (tid & 63) * 4 + (kseg * 128) * 512;

    // clamped global row index per local row (last CTA: rows 5,6 -> 1023)
    int grow[ROWS];
#pragma unroll
    for (int r = 0; r < ROWS; ++r)
        grow[r] = (row0 + r < BB) ? (row0 + r) : (BB - 1);

    // cache small vectors; load z0 (NTH==DZc: i == local row)
#pragma unroll
    for (int i = 0; i < 4; ++i) {
        wt_s[i * NTH + tid] = wt[i * NTH + tid];
        b1_s[i * NTH + tid] = b1[i * NTH + tid];
    }
    b2_s[tid] = b2[tid];
#pragma unroll
    for (int i = 0; i < ROWS; ++i)
        z_s[i * DZc + tid] = z0[grow[i] * DZc + tid];
    __syncthreads();

    for (int step = 0; step < TT - 1; ++step) {
        const float t0 = __ldg(t + step);
        const float t1 = __ldg(t + step + 1);
        const float hstep = t1 - t0;
        const float tmid  = t0 + 0.5f * hstep;

        // stage x[step] rows [7][64]
#pragma unroll
        for (int i = 0; i < 2; ++i) {
            const int p = i * NTH + tid;           // [0, 512)
            const int r = p >> 6, d = p & 63;
            if (r < ROWS)
                xs_s[r * DXc + d] = x[(step * BB + ((row0 + r < BB) ? row0 + r : BB - 1)) * DXc + d];
        }
        __syncthreads();

        // ---- xb = x @ Wx + b1 ----
        {
            u64 a0[ROWS], a1[ROWS], a2[ROWS], a3[ROWS];
            gemm_acc4<DXc, DXc, 2 * DHc, DHc>(xs_s, wxcol, a0, a1, a2, a3);
            const float4 bb = *(const float4*)(b1_s + c0);
#pragma unroll
            for (int r = 0; r < ROWS; ++r) {
                const float2 v0 = unpack2(a0[r]);
                const float2 v1 = unpack2(a1[r]);
                const float2 v2 = unpack2(a2[r]);
                const float2 v3 = unpack2(a3[r]);
                *(float4*)(xb_s + r * DHc + c0) =
                    make_float4(v0.x + v0.y + bb.x, v1.x + v1.y + bb.y,
                                v2.x + v2.y + bb.z, v3.x + v3.y + bb.w);
            }
        }
        // no barrier: each thread reads back only its own xb columns

#pragma unroll 1
        for (int sub = 0; sub < 4; ++sub) {
            const float ts = (sub == 0) ? t0 : (sub == 3 ? t1 : tmid);
            const float* zi = (sub == 0) ? z_s : zin_s;

            // GEMM1 + fused tanh -> h_s
            {
                u64 a0[ROWS], a1[ROWS], a2[ROWS], a3[ROWS];
                gemm_acc4<DZc, DZc, 2 * DHc, DHc>(zi, w1col, a0, a1, a2, a3);
                const float4 wtv = *(const float4*)(wt_s + c0);
                const float w0 = wtv.x * ts, w1 = wtv.y * ts;
                const float w2 = wtv.z * ts, w3 = wtv.w * ts;
#pragma unroll
                for (int r = 0; r < ROWS; ++r) {
                    const float2 v0  = unpack2(a0[r]);
                    const float2 v1  = unpack2(a1[r]);
                    const float2 v2  = unpack2(a2[r]);
                    const float2 v3  = unpack2(a3[r]);
                    const float4 xbv = *(const float4*)(xb_s + r * DHc + c0);
                    *(float4*)(h_s + r * DHc + c0) =
                        make_float4(fast_tanh(v0.x + v0.y + xbv.x + w0),
                                    fast_tanh(v1.x + v1.y + xbv.y + w1),
                                    fast_tanh(v2.x + v2.y + xbv.z + w2),
                                    fast_tanh(v3.x + v3.y + xbv.w + w3));
                }
            }
            // kseg g reads h cols [256g,256g+256) written by these same 64 threads
            asm volatile("bar.sync %0, 64;" :: "r"(kseg + 1) : "memory");

            // GEMM2 (k band 256) -> partial
            {
                u64 a0[ROWS], a1[ROWS], a2[ROWS], a3[ROWS];
                gemm_acc4<256, DHc, 2 * DZc, DZc>(h_s + kseg * 256, w2col, a0, a1, a2, a3);
#pragma unroll
                for (int r = 0; r < ROWS; ++r) {
                    const float2 v0 = unpack2(a0[r]);
                    const float2 v1 = unpack2(a1[r]);
                    const float2 v2 = unpack2(a2[r]);
                    const float2 v3 = unpack2(a3[r]);
                    *(float4*)(part_s + kseg * NZ + r * DZc + j0) =
                        make_float4(v0.x + v0.y, v1.x + v1.y,
                                    v2.x + v2.y, v3.x + v3.y);
                }
            }
            __syncthreads();

            // combine 4 partials + RK4 update: thread owns col tid of all 7 rows
            // (scalar accesses, warp-contiguous -> 1 wavefront each)
            {
                const float bb = b2_s[tid];
#pragma unroll
                for (int r = 0; r < ROWS; ++r) {
                    const int p = r * DZc + tid;
                    const float v = part_s[p] + part_s[NZ + p] +
                                    part_s[2 * NZ + p] + part_s[3 * NZ + p] + bb;
                    const float zv = z_s[p];
                    if (sub == 0) {
                        ksum_s[p] = v;
                        zin_s[p]  = zv + 0.5f * hstep * v;
                    } else if (sub == 1) {
                        ksum_s[p] += 2.f * v;
                        zin_s[p]  = zv + 0.5f * hstep * v;
                    } else if (sub == 2) {
                        ksum_s[p] += 2.f * v;
                        zin_s[p]  = zv + hstep * v;
                    } else {
                        z_s[p] = zv + (hstep * (1.f / 6.f)) * (ksum_s[p] + v);
                    }
                }
            }
            __syncthreads();
        }
    }

    // write z_final (skip clamped duplicate rows)
#pragma unroll
    for (int i = 0; i < ROWS; ++i)
        if (row0 + i < BB)
            out[(row0 + i) * DZc + tid] = z_s[i * DZc + tid];
}

extern "C" void kernel_launch(void* const* d_in, const int* in_sizes, int n_in,
                              void* d_out, int out_size)
{
    const float* z0 = (const float*)d_in[0];
    const float* t  = (const float*)d_in[1];
    const float* x  = (const float*)d_in[2];
    const float* W1 = (const float*)d_in[3];
    const float* Wx = (const float*)d_in[4];
    const float* wt = (const float*)d_in[5];
    const float* b1 = (const float*)d_in[6];
    const float* W2 = (const float*)d_in[7];
    const float* b2 = (const float*)d_in[8];
    float* out = (float*)d_out;

    pack_kernel<<<(DZc * DHc) / 256, 256>>>(W1, Wx, W2);

    const size_t smem = SMEM_FLOATS * sizeof(float);   // ~116 KB
    cudaFuncSetAttribute(ode_kernel,
                         cudaFuncAttributeMaxDynamicSharedMemorySize, (int)smem);
    ode_kernel<<<NCTA, NTH, smem>>>(z0, t, x, wt, b1, b2, out);
}